// round 1
// baseline (speedup 1.0000x reference)
#include <cuda_runtime.h>

#define BATCH 512
#define TLEN 16385
#define NN 16384
#define THREADS 1024
#define EPT 16

__device__ __forceinline__ float warp_iscan(float v, unsigned lane) {
    #pragma unroll
    for (int d = 1; d < 32; d <<= 1) {
        float n = __shfl_up_sync(0xffffffffu, v, d);
        if (lane >= d) v += n;
    }
    return v;
}

__global__ __launch_bounds__(THREADS, 1)
void vp_kernel(const float* __restrict__ x, const float* __restrict__ params,
               float* __restrict__ o_coeffs, float* __restrict__ o_xhat,
               float* __restrict__ o_res, float* __restrict__ o_r2)
{
    extern __shared__ float xs[];            // 17409 floats, stride-17 padded
    __shared__ float warp_tot[32];
    __shared__ float warp_scan[32];
    __shared__ float red[32 * 5];
    __shared__ float cbc[2];

    const int tid  = threadIdx.x;
    const int lane = tid & 31;
    const int wid  = tid >> 5;
    const int b    = blockIdx.x;
    const float* __restrict__ xr = x + (size_t)b * TLEN;
    const float r  = params[0];
    const float ny = params[1];
    const bool rhalf = (r == 0.5f);

    // ---- Phase A: stage x row into padded smem (coalesced LDG, pad avoids
    //      bank conflicts on the blocked re-read: pos(j) = j + j/16) ----
    #pragma unroll
    for (int k = 0; k < 16; k++) {
        int j = k * 1024 + tid;
        xs[j + (j >> 4)] = xr[j];
    }
    if (tid == 0) { int j = NN; xs[j + (j >> 4)] = xr[j]; }
    __syncthreads();

    // Blocked chunk into registers: x[t*16 .. t*16+16] at smem stride 17
    float xv[EPT + 1];
    #pragma unroll
    for (int k = 0; k < 16; k++) xv[k] = xs[tid * 17 + k];
    xv[16] = xs[tid * 17 + 17];

    // ---- Phase B: block-wide prefix sum of trapezoid increments ----
    float tot = 0.f;
    #pragma unroll
    for (int k = 0; k < 16; k++) tot += 0.5f * (xv[k] + xv[k + 1]);

    float incw = warp_iscan(tot, lane);
    if (lane == 31) warp_tot[wid] = incw;
    __syncthreads();
    if (wid == 0) warp_scan[lane] = warp_iscan(warp_tot[lane], lane);
    __syncthreads();
    const float base = (incw - tot) + (wid ? warp_scan[wid - 1] : 0.f);

    // ---- Phase C: 5 streaming reductions over u, sqrt(u), xd ----
    float ua = ny + base;
    float s_uu = 0.f, s_u15 = 0.f, s_u = 0.f, sd0 = 0.f, sd1 = 0.f;
    #pragma unroll
    for (int k = 0; k < 16; k++) {
        ua += 0.5f * (xv[k] + xv[k + 1]);
        float u  = ua;
        float su = rhalf ? sqrtf(u) : powf(u, r);
        float xd = xv[k + 1];
        s_uu  += u * u;
        s_u15 += u * su;
        s_u   += u;
        sd0   += xd * u;
        sd1   += xd * su;
    }
    #pragma unroll
    for (int d = 16; d; d >>= 1) {
        s_uu  += __shfl_xor_sync(~0u, s_uu,  d);
        s_u15 += __shfl_xor_sync(~0u, s_u15, d);
        s_u   += __shfl_xor_sync(~0u, s_u,   d);
        sd0   += __shfl_xor_sync(~0u, sd0,   d);
        sd1   += __shfl_xor_sync(~0u, sd1,   d);
    }
    if (lane == 0) {
        red[wid * 5 + 0] = s_uu;  red[wid * 5 + 1] = s_u15;
        red[wid * 5 + 2] = s_u;   red[wid * 5 + 3] = sd0;
        red[wid * 5 + 4] = sd1;
    }
    __syncthreads();

    // ---- Rank-1 pinv solve (JAX pinv rcond = 10*N*eps truncates sigma_2) ----
    if (tid == 0) {
        double A = 0, Bb = 0, C = 0, D0 = 0, D1 = 0;
        for (int w = 0; w < 32; w++) {
            A  += red[w * 5 + 0];
            Bb += red[w * 5 + 1];
            C  += red[w * 5 + 2];
            D0 += red[w * 5 + 3];
            D1 += red[w * 5 + 4];
        }
        double h   = 0.5 * (A - C);
        double s   = sqrt(h * h + Bb * Bb);
        double lam = 0.5 * (A + C) + s;          // lambda_1 of Gram
        double w0  = Bb;
        double w1  = Bb * Bb / (h + s);          // = lam - A, stable form
        double n2  = w0 * w0 + w1 * w1;
        double beta = (w0 * D0 + w1 * D1) / (lam * n2);
        float c0 = (float)(beta * w0);
        float c1 = (float)(beta * w1);
        cbc[0] = c0; cbc[1] = c1;
        o_coeffs[b * 2 + 0] = c0;
        o_coeffs[b * 2 + 1] = c1;
    }
    __syncthreads();
    const float c0 = cbc[0];
    const float c1 = cbc[1];

    // ---- Phase D: x_hat, res (vectorized stores), r2 reduction ----
    ua = ny + base;
    float r2acc = 0.f;
    float4* __restrict__ xh4 = (float4*)(o_xhat + (size_t)b * NN);
    float4* __restrict__ rs4 = (float4*)(o_res  + (size_t)b * NN);
    #pragma unroll
    for (int q = 0; q < 4; q++) {
        float hv[4], rv[4];
        #pragma unroll
        for (int m = 0; m < 4; m++) {
            int k = q * 4 + m;
            ua += 0.5f * (xv[k] + xv[k + 1]);
            float u  = ua;
            float su = rhalf ? sqrtf(u) : powf(u, r);
            float xh = fmaf(c0, u, c1 * su);
            float rr = xv[k + 1] - xh;
            hv[m] = xh; rv[m] = rr;
            r2acc = fmaf(rr, rr, r2acc);
        }
        xh4[tid * 4 + q] = make_float4(hv[0], hv[1], hv[2], hv[3]);
        rs4[tid * 4 + q] = make_float4(rv[0], rv[1], rv[2], rv[3]);
    }
    #pragma unroll
    for (int d = 16; d; d >>= 1) r2acc += __shfl_xor_sync(~0u, r2acc, d);
    __syncthreads();                 // red[] reuse: phase-C consumers done
    if (lane == 0) red[wid] = r2acc;
    __syncthreads();
    if (tid == 0) {
        float acc = 0.f;
        for (int w = 0; w < 32; w++) acc += red[w];
        o_r2[b] = acc;
    }
}

extern "C" void kernel_launch(void* const* d_in, const int* in_sizes, int n_in,
                              void* d_out, int out_size)
{
    const float* x      = (const float*)d_in[0];
    const float* params = (const float*)d_in[1];
    if (n_in >= 2 && in_sizes[0] == 2) {       // defensive: metadata order swap
        x      = (const float*)d_in[1];
        params = (const float*)d_in[0];
    }
    float* out      = (float*)d_out;
    float* o_coeffs = out;                                   // 512*1*2
    float* o_xhat   = out + (size_t)BATCH * 2;               // 512*1*16384
    float* o_res    = o_xhat + (size_t)BATCH * NN;           // 512*1*16384
    float* o_r2     = o_res  + (size_t)BATCH * NN;           // 512*1

    size_t smem = 17409 * sizeof(float);
    cudaFuncSetAttribute(vp_kernel, cudaFuncAttributeMaxDynamicSharedMemorySize,
                         (int)smem);
    vp_kernel<<<BATCH, THREADS, smem>>>(x, params, o_coeffs, o_xhat, o_res, o_r2);
}

// round 4
// speedup vs baseline: 1.5313x; 1.5313x over previous
#include <cuda_runtime.h>

#define BATCH 512
#define TLEN 16385
#define NN 16384
#define THREADS 512
#define EPT 32
#define NWARP 16
#define PADI(j) ((j) + ((j) >> 5))
#define SMEM_FLOATS (PADI(NN) + 1)          // 16896 + 1 = 16897

__device__ __forceinline__ float warp_iscan(float v, unsigned lane) {
    #pragma unroll
    for (int d = 1; d < 32; d <<= 1) {
        float n = __shfl_up_sync(0xffffffffu, v, d);
        if (lane >= d) v += n;
    }
    return v;
}

__global__ __launch_bounds__(THREADS, 2)
void vp_kernel(const float* __restrict__ x, const float* __restrict__ params,
               float* __restrict__ o_coeffs, float* __restrict__ o_xhat,
               float* __restrict__ o_res, float* __restrict__ o_r2)
{
    extern __shared__ float xs[];           // padded row stage
    __shared__ float warp_tot[NWARP];
    __shared__ float warp_scan[NWARP];
    __shared__ float red[NWARP * 5];
    __shared__ float cbc[2];

    const int tid  = threadIdx.x;
    const int lane = tid & 31;
    const int wid  = tid >> 5;
    const int b    = blockIdx.x;
    const float* __restrict__ xr = x + (size_t)b * TLEN;
    const float r  = params[0];
    const float ny = params[1];
    const bool rhalf = (r == 0.5f);

    // ---- Phase A: coalesced scalar stage gmem -> padded smem ----
    #pragma unroll
    for (int k = 0; k < 32; k++) {
        int j = k * THREADS + tid;
        xs[PADI(j)] = xr[j];
    }
    if (tid == 0) xs[PADI(NN)] = xr[NN];
    __syncthreads();

    // Thread t owns x[32t .. 32t+32]; smem addr = 33t + k (conflict-free)
    const int sb = 33 * tid;

    // ---- Phase B: per-thread trapezoid total, then block scan ----
    float tot;
    {
        float acc = 0.5f * (xs[sb] + xs[sb + 33]);   // k=32 boundary at 33(t+1)
        #pragma unroll
        for (int k = 1; k < 32; k++) acc += xs[sb + k];
        tot = acc;
    }
    float incw = warp_iscan(tot, lane);
    if (lane == 31) warp_tot[wid] = incw;
    __syncthreads();
    if (wid == 0) {
        // ALL 32 lanes participate in the sync-shuffle scan (lanes >=16 add 0);
        // divergent full-mask shfl deadlocks on sm_103a.
        float v = (lane < NWARP) ? warp_tot[lane] : 0.f;
        v = warp_iscan(v, lane);
        if (lane < NWARP) warp_scan[lane] = v;
    }
    __syncthreads();
    const float base = (incw - tot) + (wid ? warp_scan[wid - 1] : 0.f);

    // ---- Phase C: streaming reductions Sum{u^2, u^(1+r), u, xd*u, xd*u^r} ----
    float ua = ny + base;
    float s_uu = 0.f, s_u15 = 0.f, s_u = 0.f, sd0 = 0.f, sd1 = 0.f;
    {
        float xp = xs[sb];
        #pragma unroll
        for (int k = 0; k < EPT; k++) {
            float xc = (k == 31) ? xs[sb + 33] : xs[sb + k + 1];
            ua += 0.5f * (xp + xc);
            float u  = ua;
            float su = rhalf ? sqrtf(u) : exp2f(r * __log2f(u));
            s_uu  = fmaf(u, u, s_uu);
            s_u15 = fmaf(u, su, s_u15);
            s_u  += u;
            sd0   = fmaf(xc, u, sd0);
            sd1   = fmaf(xc, su, sd1);
            xp = xc;
        }
    }
    #pragma unroll
    for (int d = 16; d; d >>= 1) {
        s_uu  += __shfl_xor_sync(~0u, s_uu,  d);
        s_u15 += __shfl_xor_sync(~0u, s_u15, d);
        s_u   += __shfl_xor_sync(~0u, s_u,   d);
        sd0   += __shfl_xor_sync(~0u, sd0,   d);
        sd1   += __shfl_xor_sync(~0u, sd1,   d);
    }
    if (lane == 0) {
        red[wid * 5 + 0] = s_uu;  red[wid * 5 + 1] = s_u15;
        red[wid * 5 + 2] = s_u;   red[wid * 5 + 3] = sd0;
        red[wid * 5 + 4] = sd1;
    }
    __syncthreads();

    // ---- Rank-1 pinv solve (JAX pinv rcond = 10*N*eps kills sigma_2) ----
    if (tid == 0) {
        double A = 0, Bb = 0, C = 0, D0 = 0, D1 = 0;
        for (int w = 0; w < NWARP; w++) {
            A  += red[w * 5 + 0];
            Bb += red[w * 5 + 1];
            C  += red[w * 5 + 2];
            D0 += red[w * 5 + 3];
            D1 += red[w * 5 + 4];
        }
        double h   = 0.5 * (A - C);
        double s   = sqrt(h * h + Bb * Bb);
        double lam = 0.5 * (A + C) + s;          // lambda_1 of Gram
        double w0  = Bb;
        double w1  = Bb * Bb / (h + s);          // = lam - A, stable form
        double n2  = w0 * w0 + w1 * w1;
        double beta = (w0 * D0 + w1 * D1) / (lam * n2);
        float c0 = (float)(beta * w0);
        float c1 = (float)(beta * w1);
        cbc[0] = c0; cbc[1] = c1;
        o_coeffs[b * 2 + 0] = c0;
        o_coeffs[b * 2 + 1] = c1;
    }
    __syncthreads();
    const float c0 = cbc[0];
    const float c1 = cbc[1];

    // ---- Phase D: x_hat, res (float4 stores, aligned), r2 ----
    ua = ny + base;
    float r2acc = 0.f;
    float4* __restrict__ xh4 = (float4*)(o_xhat + (size_t)b * NN);
    float4* __restrict__ rs4 = (float4*)(o_res  + (size_t)b * NN);
    {
        float xp = xs[sb];
        #pragma unroll
        for (int q = 0; q < 8; q++) {
            float hv[4], rv[4];
            #pragma unroll
            for (int m = 0; m < 4; m++) {
                int k = q * 4 + m;
                float xc = (k == 31) ? xs[sb + 33] : xs[sb + k + 1];
                ua += 0.5f * (xp + xc);
                float u  = ua;
                float su = rhalf ? sqrtf(u) : exp2f(r * __log2f(u));
                float xh = fmaf(c0, u, c1 * su);
                float rr = xc - xh;
                hv[m] = xh; rv[m] = rr;
                r2acc = fmaf(rr, rr, r2acc);
                xp = xc;
            }
            xh4[tid * 8 + q] = make_float4(hv[0], hv[1], hv[2], hv[3]);
            rs4[tid * 8 + q] = make_float4(rv[0], rv[1], rv[2], rv[3]);
        }
    }
    #pragma unroll
    for (int d = 16; d; d >>= 1) r2acc += __shfl_xor_sync(~0u, r2acc, d);
    __syncthreads();                 // red[] reuse safe: prior consumers done
    if (lane == 0) red[wid] = r2acc;
    __syncthreads();
    if (tid == 0) {
        float acc = 0.f;
        for (int w = 0; w < NWARP; w++) acc += red[w];
        o_r2[b] = acc;
    }
}

extern "C" void kernel_launch(void* const* d_in, const int* in_sizes, int n_in,
                              void* d_out, int out_size)
{
    const float* x      = (const float*)d_in[0];
    const float* params = (const float*)d_in[1];
    if (n_in >= 2 && in_sizes[0] == 2) {       // defensive: metadata order swap
        x      = (const float*)d_in[1];
        params = (const float*)d_in[0];
    }
    float* out      = (float*)d_out;
    float* o_coeffs = out;                                   // 512*1*2
    float* o_xhat   = out + (size_t)BATCH * 2;               // 512*1*16384
    float* o_res    = o_xhat + (size_t)BATCH * NN;           // 512*1*16384
    float* o_r2     = o_res  + (size_t)BATCH * NN;           // 512*1

    size_t smem = SMEM_FLOATS * sizeof(float);
    cudaFuncSetAttribute(vp_kernel, cudaFuncAttributeMaxDynamicSharedMemorySize,
                         (int)smem);
    vp_kernel<<<BATCH, THREADS, smem>>>(x, params, o_coeffs, o_xhat, o_res, o_r2);
}

// round 5
// speedup vs baseline: 1.5467x; 1.0101x over previous
#include <cuda_runtime.h>

#define BATCH 512
#define TLEN 16385
#define NN 16384
#define THREADS 256
#define EPT 64
#define NWARP 8
#define PADI(j) ((j) + ((j) >> 6))
#define SMEM_FLOATS (PADI(NN) + 1)          // 16384 + 256 + 1 = 16641 (66.6KB)

__device__ __forceinline__ float warp_iscan(float v, unsigned lane) {
    #pragma unroll
    for (int d = 1; d < 32; d <<= 1) {
        float n = __shfl_up_sync(0xffffffffu, v, d);
        if (lane >= d) v += n;
    }
    return v;
}

__global__ __launch_bounds__(THREADS, 3)
void vp_kernel(const float* __restrict__ x, const float* __restrict__ params,
               float* __restrict__ o_coeffs, float* __restrict__ o_xhat,
               float* __restrict__ o_res, float* __restrict__ o_r2)
{
    extern __shared__ float xs[];           // padded row stage, pad 1 per 64
    __shared__ float warp_tot[NWARP];
    __shared__ float warp_scan[NWARP];
    __shared__ float red[NWARP * 5];
    __shared__ float cbc[2];

    const int tid  = threadIdx.x;
    const int lane = tid & 31;
    const int wid  = tid >> 5;
    const int b    = blockIdx.x;
    const float* __restrict__ xr = x + (size_t)b * TLEN;
    const float r  = params[0];
    const float ny = params[1];
    const bool rhalf = (r == 0.5f);

    // ---- Phase A: coalesced scalar stage gmem -> padded smem ----
    // Warp spans 32 consecutive j; c mod 64 in {0,32} so no pad crossing
    // inside a warp -> conflict-free STS.
    #pragma unroll
    for (int k = 0; k < EPT; k++) {
        int j = k * THREADS + tid;
        xs[PADI(j)] = xr[j];
    }
    if (tid == 0) xs[PADI(NN)] = xr[NN];
    __syncthreads();

    // Thread t owns x[64t .. 64t+64]; smem addr = 65t + k.
    // Lane stride 65 === 1 (mod 32) -> conflict-free LDS.
    const int sb = 65 * tid;

    // ---- Phase B: per-thread trapezoid total, then block scan ----
    float tot;
    {
        float acc = 0.5f * (xs[sb] + xs[sb + 65]);   // k=64 boundary at 65(t+1)
        #pragma unroll
        for (int k = 1; k < EPT; k++) acc += xs[sb + k];
        tot = acc;
    }
    float incw = warp_iscan(tot, lane);
    if (lane == 31) warp_tot[wid] = incw;
    __syncthreads();
    if (wid == 0) {
        // ALL 32 lanes run the sync-shuffle scan (lanes >= NWARP add 0);
        // divergent full-mask shfl deadlocks on sm_103a.
        float v = (lane < NWARP) ? warp_tot[lane] : 0.f;
        v = warp_iscan(v, lane);
        if (lane < NWARP) warp_scan[lane] = v;
    }
    __syncthreads();
    const float base = (incw - tot) + (wid ? warp_scan[wid - 1] : 0.f);

    // ---- Phase C: streaming reductions Sum{u^2, u^(1+r), u, xd*u, xd*u^r} ----
    float ua = ny + base;
    float s_uu = 0.f, s_u15 = 0.f, s_u = 0.f, sd0 = 0.f, sd1 = 0.f;
    {
        float xp = xs[sb];
        #pragma unroll
        for (int k = 0; k < EPT; k++) {
            float xc = (k == EPT - 1) ? xs[sb + 65] : xs[sb + k + 1];
            ua += 0.5f * (xp + xc);
            float u  = ua;
            float su = rhalf ? sqrtf(u) : exp2f(r * __log2f(u));
            s_uu  = fmaf(u, u, s_uu);
            s_u15 = fmaf(u, su, s_u15);
            s_u  += u;
            sd0   = fmaf(xc, u, sd0);
            sd1   = fmaf(xc, su, sd1);
            xp = xc;
        }
    }
    #pragma unroll
    for (int d = 16; d; d >>= 1) {
        s_uu  += __shfl_xor_sync(~0u, s_uu,  d);
        s_u15 += __shfl_xor_sync(~0u, s_u15, d);
        s_u   += __shfl_xor_sync(~0u, s_u,   d);
        sd0   += __shfl_xor_sync(~0u, sd0,   d);
        sd1   += __shfl_xor_sync(~0u, sd1,   d);
    }
    if (lane == 0) {
        red[wid * 5 + 0] = s_uu;  red[wid * 5 + 1] = s_u15;
        red[wid * 5 + 2] = s_u;   red[wid * 5 + 3] = sd0;
        red[wid * 5 + 4] = sd1;
    }
    __syncthreads();

    // ---- Rank-1 pinv solve (JAX pinv rcond = 10*N*eps kills sigma_2) ----
    if (tid == 0) {
        double A = 0, Bb = 0, C = 0, D0 = 0, D1 = 0;
        for (int w = 0; w < NWARP; w++) {
            A  += red[w * 5 + 0];
            Bb += red[w * 5 + 1];
            C  += red[w * 5 + 2];
            D0 += red[w * 5 + 3];
            D1 += red[w * 5 + 4];
        }
        double h   = 0.5 * (A - C);
        double s   = sqrt(h * h + Bb * Bb);
        double lam = 0.5 * (A + C) + s;          // lambda_1 of Gram
        double w0  = Bb;
        double w1  = Bb * Bb / (h + s);          // = lam - A, stable form
        double n2  = w0 * w0 + w1 * w1;
        double beta = (w0 * D0 + w1 * D1) / (lam * n2);
        float c0 = (float)(beta * w0);
        float c1 = (float)(beta * w1);
        cbc[0] = c0; cbc[1] = c1;
        o_coeffs[b * 2 + 0] = c0;
        o_coeffs[b * 2 + 1] = c1;
    }
    __syncthreads();
    const float c0 = cbc[0];
    const float c1 = cbc[1];

    // ---- Phase D: x_hat, res (float4 stores, aligned), r2 ----
    ua = ny + base;
    float r2acc = 0.f;
    float4* __restrict__ xh4 = (float4*)(o_xhat + (size_t)b * NN);
    float4* __restrict__ rs4 = (float4*)(o_res  + (size_t)b * NN);
    {
        float xp = xs[sb];
        #pragma unroll
        for (int q = 0; q < EPT / 4; q++) {
            float hv[4], rv[4];
            #pragma unroll
            for (int m = 0; m < 4; m++) {
                int k = q * 4 + m;
                float xc = (k == EPT - 1) ? xs[sb + 65] : xs[sb + k + 1];
                ua += 0.5f * (xp + xc);
                float u  = ua;
                float su = rhalf ? sqrtf(u) : exp2f(r * __log2f(u));
                float xh = fmaf(c0, u, c1 * su);
                float rr = xc - xh;
                hv[m] = xh; rv[m] = rr;
                r2acc = fmaf(rr, rr, r2acc);
                xp = xc;
            }
            xh4[tid * (EPT / 4) + q] = make_float4(hv[0], hv[1], hv[2], hv[3]);
            rs4[tid * (EPT / 4) + q] = make_float4(rv[0], rv[1], rv[2], rv[3]);
        }
    }
    #pragma unroll
    for (int d = 16; d; d >>= 1) r2acc += __shfl_xor_sync(~0u, r2acc, d);
    __syncthreads();                 // red[] reuse safe: prior consumers done
    if (lane == 0) red[wid] = r2acc;
    __syncthreads();
    if (tid == 0) {
        float acc = 0.f;
        for (int w = 0; w < NWARP; w++) acc += red[w];
        o_r2[b] = acc;
    }
}

extern "C" void kernel_launch(void* const* d_in, const int* in_sizes, int n_in,
                              void* d_out, int out_size)
{
    const float* x      = (const float*)d_in[0];
    const float* params = (const float*)d_in[1];
    if (n_in >= 2 && in_sizes[0] == 2) {       // defensive: metadata order swap
        x      = (const float*)d_in[1];
        params = (const float*)d_in[0];
    }
    float* out      = (float*)d_out;
    float* o_coeffs = out;                                   // 512*1*2
    float* o_xhat   = out + (size_t)BATCH * 2;               // 512*1*16384
    float* o_res    = o_xhat + (size_t)BATCH * NN;           // 512*1*16384
    float* o_r2     = o_res  + (size_t)BATCH * NN;           // 512*1

    size_t smem = SMEM_FLOATS * sizeof(float);
    cudaFuncSetAttribute(vp_kernel, cudaFuncAttributeMaxDynamicSharedMemorySize,
                         (int)smem);
    vp_kernel<<<BATCH, THREADS, smem>>>(x, params, o_coeffs, o_xhat, o_res, o_r2);
}

// round 6
// speedup vs baseline: 1.7944x; 1.1602x over previous
#include <cuda_runtime.h>

#define BATCH 512
#define TLEN 16385
#define NN 16384
#define THREADS 256
#define HALF 8192
#define EPT 32
#define NWARP 8
#define PAD(j) ((j) + ((j) >> 5))
#define SMEM_FLOATS (PAD(HALF) + 1)      // 8448 + 1 = 8449 floats = 33.8KB

__device__ __forceinline__ float fsqrt_a(float v) {
    float r; asm("sqrt.approx.f32 %0, %1;" : "=f"(r) : "f"(v)); return r;
}
__device__ __forceinline__ float fex2_a(float v) {
    float r; asm("ex2.approx.f32 %0, %1;" : "=f"(r) : "f"(v)); return r;
}
__device__ __forceinline__ float flg2_a(float v) {
    float r; asm("lg2.approx.f32 %0, %1;" : "=f"(r) : "f"(v)); return r;
}

__device__ __forceinline__ float warp_iscan(float v, unsigned lane) {
    #pragma unroll
    for (int d = 1; d < 32; d <<= 1) {
        float n = __shfl_up_sync(0xffffffffu, v, d);
        if (lane >= d) v += n;
    }
    return v;
}

__global__ __launch_bounds__(THREADS, 4)
void vp_kernel(const float* __restrict__ x, const float* __restrict__ params,
               float* __restrict__ o_coeffs, float* __restrict__ o_xhat,
               float* __restrict__ o_res, float* __restrict__ o_r2)
{
    extern __shared__ float xs[];            // half-row stage, pad 1/32
    __shared__ float warp_tot[NWARP];
    __shared__ float warp_scan[NWARP];
    __shared__ float red[NWARP * 6];
    __shared__ float cbc[2];

    const int tid  = threadIdx.x;
    const int lane = tid & 31;
    const int wid  = tid >> 5;
    const int b    = blockIdx.x;
    const float* __restrict__ xr = x + (size_t)b * TLEN;
    const float r  = params[0];
    const float ny = params[1];
    const bool rhalf = (r == 0.5f);

    const int sb = 33 * tid;                 // blocked smem base, stride 33
    float base[2];                           // per-half u offset for this thread
    float uoff = ny;
    float sA = 0.f, sB = 0.f, sC = 0.f, sD0 = 0.f, sD1 = 0.f, sE = 0.f;

    // ================= Reduction passes over both halves =================
    #pragma unroll 1
    for (int h = 0; h < 2; h++) {
        const float* __restrict__ xh = xr + h * HALF;
        // stage: coalesced scalar -> padded smem (warp spans one 32-block: no
        // pad crossing; blocked re-read stride 33 === 1 mod 32: conflict-free)
        #pragma unroll
        for (int k = 0; k < EPT; k++) {
            int j = k * THREADS + tid;
            xs[PAD(j)] = xh[j];
        }
        if (tid == 0) xs[PAD(HALF)] = xh[HALF];
        __syncthreads();

        // per-thread trapezoid total over x[32t .. 32t+32] of this half
        float tot = 0.5f * (xs[sb] + xs[sb + 33]);
        #pragma unroll
        for (int k = 1; k < EPT; k++) tot += xs[sb + k];

        float incw = warp_iscan(tot, lane);
        if (lane == 31) warp_tot[wid] = incw;
        __syncthreads();
        if (wid == 0) {
            // all 32 lanes run the full-mask shfl scan (lanes >= NWARP add 0)
            float v = (lane < NWARP) ? warp_tot[lane] : 0.f;
            v = warp_iscan(v, lane);
            if (lane < NWARP) warp_scan[lane] = v;
        }
        __syncthreads();
        const float bs = uoff + (incw - tot) + (wid ? warp_scan[wid - 1] : 0.f);
        base[h] = bs;

        // streaming sums: A=Su^2 B=Su^(1+r) C=Su D0=Sxd*u D1=Sxd*u^r E=Sxd^2
        float ua = bs;
        float xp = xs[sb];
        #pragma unroll
        for (int k = 0; k < EPT; k++) {
            float xc = (k == EPT - 1) ? xs[sb + 33] : xs[sb + k + 1];
            ua += 0.5f * (xp + xc);
            float u  = ua;
            float su = rhalf ? fsqrt_a(u) : fex2_a(r * flg2_a(u));
            sA  = fmaf(u, u, sA);
            sB  = fmaf(u, su, sB);
            sC += u;
            sD0 = fmaf(xc, u, sD0);
            sD1 = fmaf(xc, su, sD1);
            sE  = fmaf(xc, xc, sE);
            xp = xc;
        }
        uoff += warp_scan[NWARP - 1];        // half total
        __syncthreads();                     // smem reads done before restage
    }

    // ================= Block reduce + rank-1 pinv solve =================
    #pragma unroll
    for (int d = 16; d; d >>= 1) {
        sA  += __shfl_xor_sync(~0u, sA,  d);
        sB  += __shfl_xor_sync(~0u, sB,  d);
        sC  += __shfl_xor_sync(~0u, sC,  d);
        sD0 += __shfl_xor_sync(~0u, sD0, d);
        sD1 += __shfl_xor_sync(~0u, sD1, d);
        sE  += __shfl_xor_sync(~0u, sE,  d);
    }
    if (lane == 0) {
        red[wid * 6 + 0] = sA;  red[wid * 6 + 1] = sB;
        red[wid * 6 + 2] = sC;  red[wid * 6 + 3] = sD0;
        red[wid * 6 + 4] = sD1; red[wid * 6 + 5] = sE;
    }
    __syncthreads();
    if (tid == 0) {
        double A = 0, Bb = 0, C = 0, D0 = 0, D1 = 0, E = 0;
        for (int w = 0; w < NWARP; w++) {
            A  += red[w * 6 + 0]; Bb += red[w * 6 + 1];
            C  += red[w * 6 + 2]; D0 += red[w * 6 + 3];
            D1 += red[w * 6 + 4]; E  += red[w * 6 + 5];
        }
        // JAX pinv rcond = 10*max(M,N)*eps truncates sigma_2 -> rank-1 solve
        double hh  = 0.5 * (A - C);
        double s   = sqrt(hh * hh + Bb * Bb);
        double lam = 0.5 * (A + C) + s;          // lambda_1 of Gram
        double w0  = Bb;
        double w1  = Bb * Bb / (hh + s);         // = lam - A, stable form
        double n2  = w0 * w0 + w1 * w1;
        double beta = (w0 * D0 + w1 * D1) / (lam * n2);
        double c0d = beta * w0, c1d = beta * w1;
        float c0 = (float)c0d, c1 = (float)c1d;
        cbc[0] = c0; cbc[1] = c1;
        o_coeffs[b * 2 + 0] = c0;
        o_coeffs[b * 2 + 1] = c1;
        // analytic r2 = E - 2 c.d + c^T G c  (G = [[A,Bb],[Bb,C]])
        double r2 = E - 2.0 * (c0d * D0 + c1d * D1)
                  + (c0d * c0d * A + 2.0 * c0d * c1d * Bb + c1d * c1d * C);
        o_r2[b] = (float)r2;
    }
    __syncthreads();
    const float c0 = cbc[0];
    const float c1 = cbc[1];

    // ================= Output passes (restage halves) =================
    float4* __restrict__ xh4 = (float4*)(o_xhat + (size_t)b * NN);
    float4* __restrict__ rs4 = (float4*)(o_res  + (size_t)b * NN);
    #pragma unroll 1
    for (int h = 0; h < 2; h++) {
        const float* __restrict__ xh = xr + h * HALF;
        #pragma unroll
        for (int k = 0; k < EPT; k++) {
            int j = k * THREADS + tid;
            xs[PAD(j)] = xh[j];
        }
        if (tid == 0) xs[PAD(HALF)] = xh[HALF];
        __syncthreads();

        float ua = base[h];
        float xp = xs[sb];
        const int o4 = h * (HALF / 4) + tid * (EPT / 4);
        #pragma unroll
        for (int q = 0; q < EPT / 4; q++) {
            float hv[4], rv[4];
            #pragma unroll
            for (int m = 0; m < 4; m++) {
                int k = q * 4 + m;
                float xc = (k == EPT - 1) ? xs[sb + 33] : xs[sb + k + 1];
                ua += 0.5f * (xp + xc);
                float u  = ua;
                float su = rhalf ? fsqrt_a(u) : fex2_a(r * flg2_a(u));
                float xv = fmaf(c0, u, c1 * su);
                hv[m] = xv; rv[m] = xc - xv;
                xp = xc;
            }
            xh4[o4 + q] = make_float4(hv[0], hv[1], hv[2], hv[3]);
            rs4[o4 + q] = make_float4(rv[0], rv[1], rv[2], rv[3]);
        }
        __syncthreads();                     // reads done before next restage
    }
}

extern "C" void kernel_launch(void* const* d_in, const int* in_sizes, int n_in,
                              void* d_out, int out_size)
{
    const float* x      = (const float*)d_in[0];
    const float* params = (const float*)d_in[1];
    if (n_in >= 2 && in_sizes[0] == 2) {       // defensive: metadata order swap
        x      = (const float*)d_in[1];
        params = (const float*)d_in[0];
    }
    float* out      = (float*)d_out;
    float* o_coeffs = out;                                   // 512*1*2
    float* o_xhat   = out + (size_t)BATCH * 2;               // 512*1*16384
    float* o_res    = o_xhat + (size_t)BATCH * NN;           // 512*1*16384
    float* o_r2     = o_res  + (size_t)BATCH * NN;           // 512*1

    size_t smem = SMEM_FLOATS * sizeof(float);
    cudaFuncSetAttribute(vp_kernel, cudaFuncAttributeMaxDynamicSharedMemorySize,
                         (int)smem);
    vp_kernel<<<BATCH, THREADS, smem>>>(x, params, o_coeffs, o_xhat, o_res, o_r2);
}

// round 7
// speedup vs baseline: 1.9431x; 1.0829x over previous
#include <cuda_runtime.h>

#define BATCH 512
#define TLEN 16385
#define NN 16384
#define THREADS 256
#define HALF 8192
#define EPT 32
#define NWARP 8
#define PAD(j) ((j) + ((j) >> 5))
#define SMEM_FLOATS (PAD(HALF) + 1)      // 8448 + 1 = 8449 floats = 33.8KB

__device__ __forceinline__ float fsqrt_a(float v) {
    float r; asm("sqrt.approx.f32 %0, %1;" : "=f"(r) : "f"(v)); return r;
}
__device__ __forceinline__ float fex2_a(float v) {
    float r; asm("ex2.approx.f32 %0, %1;" : "=f"(r) : "f"(v)); return r;
}
__device__ __forceinline__ float flg2_a(float v) {
    float r; asm("lg2.approx.f32 %0, %1;" : "=f"(r) : "f"(v)); return r;
}

__device__ __forceinline__ float warp_iscan(float v, unsigned lane) {
    #pragma unroll
    for (int d = 1; d < 32; d <<= 1) {
        float n = __shfl_up_sync(0xffffffffu, v, d);
        if (lane >= d) v += n;
    }
    return v;
}

// coalesced scalar stage of one half-row (+1 boundary elem) into padded smem
__device__ __forceinline__ void stage_half(float* xs, const float* __restrict__ xh,
                                           int tid) {
    #pragma unroll
    for (int k = 0; k < EPT; k++) {
        int j = k * THREADS + tid;
        xs[PAD(j)] = xh[j];
    }
    if (tid == 0) xs[PAD(HALF)] = xh[HALF];
}

__global__ __launch_bounds__(THREADS, 4)
void vp_kernel(const float* __restrict__ x, const float* __restrict__ params,
               float* __restrict__ o_coeffs, float* __restrict__ o_xhat,
               float* __restrict__ o_res, float* __restrict__ o_r2)
{
    extern __shared__ float xs[];            // half-row stage, pad 1/32
    __shared__ float warp_tot[NWARP];
    __shared__ float warp_scan[NWARP];
    __shared__ float red[NWARP * 6];
    __shared__ float cbc[2];

    const int tid  = threadIdx.x;
    const int lane = tid & 31;
    const int wid  = tid >> 5;
    const int b    = blockIdx.x;
    const float* __restrict__ xr = x + (size_t)b * TLEN;
    const float r  = params[0];
    const float ny = params[1];
    const bool rhalf = (r == 0.5f);

    const int sb = 33 * tid;                 // blocked smem base, stride 33
    float base[2];                           // per-half u offset per thread
    float uoff = ny;
    float sA = 0.f, sB = 0.f, sC = 0.f, sD0 = 0.f, sD1 = 0.f, sE = 0.f;

    // ================= Reduction passes over both halves =================
    #pragma unroll 1
    for (int h = 0; h < 2; h++) {
        stage_half(xs, xr + h * HALF, tid);
        __syncthreads();

        // per-thread trapezoid total, 4 independent chains
        float tot;
        {
            float t0 = 0.f, t1 = 0.f, t2 = 0.f, t3 = 0.f;
            #pragma unroll
            for (int k = 1; k < 29; k += 4) {
                t0 += xs[sb + k];     t1 += xs[sb + k + 1];
                t2 += xs[sb + k + 2]; t3 += xs[sb + k + 3];
            }
            t0 += xs[sb + 29]; t1 += xs[sb + 30]; t2 += xs[sb + 31];
            tot = 0.5f * (xs[sb] + xs[sb + 33]) + ((t0 + t1) + (t2 + t3));
        }
        float incw = warp_iscan(tot, lane);
        if (lane == 31) warp_tot[wid] = incw;
        __syncthreads();
        if (wid == 0) {
            // all 32 lanes run the full-mask shfl scan (lanes >= NWARP add 0)
            float v = (lane < NWARP) ? warp_tot[lane] : 0.f;
            v = warp_iscan(v, lane);
            if (lane < NWARP) warp_scan[lane] = v;
        }
        __syncthreads();
        const float bs = uoff + (incw - tot) + (wid ? warp_scan[wid - 1] : 0.f);
        base[h] = bs;

        // streaming sums: A=Su^2 B=Su^(1+r) C=Su D0=Sxd*u D1=Sxd*u^r E=Sxd^2
        float ua = bs;
        float xp = xs[sb];
        #pragma unroll
        for (int k = 0; k < EPT; k++) {
            float xc = (k == EPT - 1) ? xs[sb + 33] : xs[sb + k + 1];
            ua += 0.5f * (xp + xc);
            float u  = ua;
            float su = rhalf ? fsqrt_a(u) : fex2_a(r * flg2_a(u));
            sA  = fmaf(u, u, sA);
            sB  = fmaf(u, su, sB);
            sC += u;
            sD0 = fmaf(xc, u, sD0);
            sD1 = fmaf(xc, su, sD1);
            sE  = fmaf(xc, xc, sE);
            xp = xc;
        }
        uoff += warp_scan[NWARP - 1];        // half total
        __syncthreads();                     // smem reads done before restage
    }

    // ================= Block reduce + rank-1 pinv solve =================
    #pragma unroll
    for (int d = 16; d; d >>= 1) {
        sA  += __shfl_xor_sync(~0u, sA,  d);
        sB  += __shfl_xor_sync(~0u, sB,  d);
        sC  += __shfl_xor_sync(~0u, sC,  d);
        sD0 += __shfl_xor_sync(~0u, sD0, d);
        sD1 += __shfl_xor_sync(~0u, sD1, d);
        sE  += __shfl_xor_sync(~0u, sE,  d);
    }
    if (lane == 0) {
        red[wid * 6 + 0] = sA;  red[wid * 6 + 1] = sB;
        red[wid * 6 + 2] = sC;  red[wid * 6 + 3] = sD0;
        red[wid * 6 + 4] = sD1; red[wid * 6 + 5] = sE;
    }
    __syncthreads();
    if (tid == 0) {
        double A = 0, Bb = 0, C = 0, D0 = 0, D1 = 0, E = 0;
        for (int w = 0; w < NWARP; w++) {
            A  += red[w * 6 + 0]; Bb += red[w * 6 + 1];
            C  += red[w * 6 + 2]; D0 += red[w * 6 + 3];
            D1 += red[w * 6 + 4]; E  += red[w * 6 + 5];
        }
        // JAX pinv rcond = 10*max(M,N)*eps truncates sigma_2 -> rank-1 solve
        double hh  = 0.5 * (A - C);
        double s   = sqrt(hh * hh + Bb * Bb);
        double lam = 0.5 * (A + C) + s;          // lambda_1 of Gram
        double w0  = Bb;
        double w1  = Bb * Bb / (hh + s);         // = lam - A, stable form
        double n2  = w0 * w0 + w1 * w1;
        double beta = (w0 * D0 + w1 * D1) / (lam * n2);
        double c0d = beta * w0, c1d = beta * w1;
        float c0 = (float)c0d, c1 = (float)c1d;
        cbc[0] = c0; cbc[1] = c1;
        o_coeffs[b * 2 + 0] = c0;
        o_coeffs[b * 2 + 1] = c1;
        // analytic r2 = E - 2 c.d + c^T G c  (G = [[A,Bb],[Bb,C]])
        double r2 = E - 2.0 * (c0d * D0 + c1d * D1)
                  + (c0d * c0d * A + 2.0 * c0d * c1d * Bb + c1d * c1d * C);
        o_r2[b] = (float)r2;
    }
    __syncthreads();
    const float c0 = cbc[0];
    const float c1 = cbc[1];

    // ================= Output passes =================
    // smem still holds half 1 -> emit h=1 first (no restage), then h=0.
    float4* __restrict__ xh4 = (float4*)(o_xhat + (size_t)b * NN);
    float4* __restrict__ rs4 = (float4*)(o_res  + (size_t)b * NN);
    #pragma unroll 1
    for (int p = 0; p < 2; p++) {
        const int h = 1 - p;                 // p=0 -> h=1 (resident), p=1 -> h=0
        if (p == 1) {
            __syncthreads();                 // prior reads done before restage
            stage_half(xs, xr, tid);         // h = 0
            __syncthreads();
        }
        float ua = base[h];
        float xp = xs[sb];
        const int o4 = h * (HALF / 4) + tid * (EPT / 4);
        #pragma unroll
        for (int q = 0; q < EPT / 4; q++) {
            float hv[4], rv[4];
            #pragma unroll
            for (int m = 0; m < 4; m++) {
                int k = q * 4 + m;
                float xc = (k == EPT - 1) ? xs[sb + 33] : xs[sb + k + 1];
                ua += 0.5f * (xp + xc);
                float u  = ua;
                float su = rhalf ? fsqrt_a(u) : fex2_a(r * flg2_a(u));
                float xv = fmaf(c0, u, c1 * su);
                hv[m] = xv; rv[m] = xc - xv;
                xp = xc;
            }
            xh4[o4 + q] = make_float4(hv[0], hv[1], hv[2], hv[3]);
            rs4[o4 + q] = make_float4(rv[0], rv[1], rv[2], rv[3]);
        }
    }
}

extern "C" void kernel_launch(void* const* d_in, const int* in_sizes, int n_in,
                              void* d_out, int out_size)
{
    const float* x      = (const float*)d_in[0];
    const float* params = (const float*)d_in[1];
    if (n_in >= 2 && in_sizes[0] == 2) {       // defensive: metadata order swap
        x      = (const float*)d_in[1];
        params = (const float*)d_in[0];
    }
    float* out      = (float*)d_out;
    float* o_coeffs = out;                                   // 512*1*2
    float* o_xhat   = out + (size_t)BATCH * 2;               // 512*1*16384
    float* o_res    = o_xhat + (size_t)BATCH * NN;           // 512*1*16384
    float* o_r2     = o_res  + (size_t)BATCH * NN;           // 512*1

    size_t smem = SMEM_FLOATS * sizeof(float);
    cudaFuncSetAttribute(vp_kernel, cudaFuncAttributeMaxDynamicSharedMemorySize,
                         (int)smem);
    vp_kernel<<<BATCH, THREADS, smem>>>(x, params, o_coeffs, o_xhat, o_res, o_r2);
}

// round 8
// speedup vs baseline: 1.9445x; 1.0007x over previous
#include <cuda_runtime.h>

#define BATCH 512
#define TLEN 16385
#define NN 16384
#define THREADS 256
#define HALF 8192
#define EPT 32
#define NWARP 8
#define PADL(j) ((j) + (((j) >> 5) << 2))      // pad 4 per 32 -> float4-friendly
#define SMEM_FLOATS (PADL(HALF) + 1)           // 9216 + 1 = 9217 (36.9KB)

__device__ __forceinline__ float fsqrt_a(float v) {
    float r; asm("sqrt.approx.f32 %0, %1;" : "=f"(r) : "f"(v)); return r;
}
__device__ __forceinline__ float fex2_a(float v) {
    float r; asm("ex2.approx.f32 %0, %1;" : "=f"(r) : "f"(v)); return r;
}
__device__ __forceinline__ float flg2_a(float v) {
    float r; asm("lg2.approx.f32 %0, %1;" : "=f"(r) : "f"(v)); return r;
}

__device__ __forceinline__ float warp_iscan(float v, unsigned lane) {
    #pragma unroll
    for (int d = 1; d < 32; d <<= 1) {
        float n = __shfl_up_sync(0xffffffffu, v, d);
        if (lane >= d) v += n;
    }
    return v;
}

// coalesced scalar stage of one half-row (+1 boundary elem) into padded smem;
// warp spans 32 consecutive j inside one 32-block -> no pad crossing, no conflicts
__device__ __forceinline__ void stage_half(float* xs, const float* __restrict__ xh,
                                           int tid) {
    #pragma unroll
    for (int k = 0; k < EPT; k++) {
        int j = k * THREADS + tid;
        xs[PADL(j)] = xh[j];
    }
    if (tid == 0) xs[PADL(HALF)] = xh[HALF];
}

__global__ __launch_bounds__(THREADS, 4)
void vp_kernel(const float* __restrict__ x, const float* __restrict__ params,
               float* __restrict__ o_coeffs, float* __restrict__ o_xhat,
               float* __restrict__ o_res, float* __restrict__ o_r2)
{
    extern __shared__ __align__(16) float xs[];
    __shared__ float warp_tot[NWARP];
    __shared__ float warp_scan[NWARP];
    __shared__ float red[NWARP * 6];
    __shared__ float cbc[2];

    const int tid  = threadIdx.x;
    const int lane = tid & 31;
    const int wid  = tid >> 5;
    const int b    = blockIdx.x;
    const float* __restrict__ xr = x + (size_t)b * TLEN;
    const float r  = params[0];
    const float ny = params[1];
    const bool rhalf = (r == 0.5f);

    // thread chunk: x[32t .. 32t+32]; smem word base 36t -> float4 base 9t
    const float4* __restrict__ xt4 = (const float4*)(xs + 36 * tid);
    const int blast = 36 * tid + 36;         // boundary elem x[32t+32]

    float base2[2];                          // per-half (bs + 0.5*x_first)
    float uoff = ny;
    float sA = 0.f, sB = 0.f, sC = 0.f, sD0 = 0.f, sD1 = 0.f, sE = 0.f;

    // ================= Reduction passes over both halves =================
    #pragma unroll 1
    for (int h = 0; h < 2; h++) {
        stage_half(xs, xr + h * HALF, tid);
        __syncthreads();

        // ---- per-thread trapezoid total: T - 0.5*f0 + 0.5*xlast ----
        float f0, tot;
        {
            float t0 = 0.f, t1 = 0.f, t2 = 0.f, t3 = 0.f;
            float4 v0 = xt4[0];
            f0 = v0.x;
            t0 = v0.x; t1 = v0.y; t2 = v0.z; t3 = v0.w;
            #pragma unroll
            for (int g = 1; g < 8; g++) {
                float4 v = xt4[g];
                t0 += v.x; t1 += v.y; t2 += v.z; t3 += v.w;
            }
            float T = (t0 + t1) + (t2 + t3);
            tot = T + 0.5f * (xs[blast] - f0);
        }
        float incw = warp_iscan(tot, lane);
        if (lane == 31) warp_tot[wid] = incw;
        __syncthreads();
        if (wid == 0) {
            // all 32 lanes run the full-mask shfl scan (lanes >= NWARP add 0)
            float v = (lane < NWARP) ? warp_tot[lane] : 0.f;
            v = warp_iscan(v, lane);
            if (lane < NWARP) warp_scan[lane] = v;
        }
        __syncthreads();
        const float bs = uoff + (incw - tot) + (wid ? warp_scan[wid - 1] : 0.f);
        const float b2 = bs + 0.5f * f0;     // u_k = b2 + ps_k - 0.5*xc_k
        base2[h] = b2;

        // ---- streaming sums: A=Su^2 B=Su^(1+r) C=Su D0=Sxd*u D1=Sxd*u^r E=Sxd^2
        float ps = 0.f;
        float4 cur = xt4[0];
        #pragma unroll
        for (int g = 0; g < 8; g++) {
            float4 nxt;
            if (g < 7) nxt = xt4[g + 1];
            else { nxt.x = xs[blast]; nxt.y = nxt.z = nxt.w = 0.f; }
            float e[4] = {cur.y, cur.z, cur.w, nxt.x};
            #pragma unroll
            for (int m = 0; m < 4; m++) {
                float xc = e[m];
                ps += xc;
                float u  = fmaf(-0.5f, xc, b2 + ps);
                float su = rhalf ? fsqrt_a(u) : fex2_a(r * flg2_a(u));
                sA  = fmaf(u, u, sA);
                sB  = fmaf(u, su, sB);
                sC += u;
                sD0 = fmaf(xc, u, sD0);
                sD1 = fmaf(xc, su, sD1);
                sE  = fmaf(xc, xc, sE);
            }
            cur = nxt;
        }
        uoff += warp_scan[NWARP - 1];        // half total
        __syncthreads();                     // smem reads done before restage
    }

    // ================= Block reduce + rank-1 pinv solve =================
    #pragma unroll
    for (int d = 16; d; d >>= 1) {
        sA  += __shfl_xor_sync(~0u, sA,  d);
        sB  += __shfl_xor_sync(~0u, sB,  d);
        sC  += __shfl_xor_sync(~0u, sC,  d);
        sD0 += __shfl_xor_sync(~0u, sD0, d);
        sD1 += __shfl_xor_sync(~0u, sD1, d);
        sE  += __shfl_xor_sync(~0u, sE,  d);
    }
    if (lane == 0) {
        red[wid * 6 + 0] = sA;  red[wid * 6 + 1] = sB;
        red[wid * 6 + 2] = sC;  red[wid * 6 + 3] = sD0;
        red[wid * 6 + 4] = sD1; red[wid * 6 + 5] = sE;
    }
    __syncthreads();
    if (tid == 0) {
        double A = 0, Bb = 0, C = 0, D0 = 0, D1 = 0, E = 0;
        for (int w = 0; w < NWARP; w++) {
            A  += red[w * 6 + 0]; Bb += red[w * 6 + 1];
            C  += red[w * 6 + 2]; D0 += red[w * 6 + 3];
            D1 += red[w * 6 + 4]; E  += red[w * 6 + 5];
        }
        // JAX pinv rcond = 10*max(M,N)*eps truncates sigma_2 -> rank-1 solve
        double hh  = 0.5 * (A - C);
        double s   = sqrt(hh * hh + Bb * Bb);
        double lam = 0.5 * (A + C) + s;          // lambda_1 of Gram
        double w0  = Bb;
        double w1  = Bb * Bb / (hh + s);         // = lam - A, stable form
        double n2  = w0 * w0 + w1 * w1;
        double beta = (w0 * D0 + w1 * D1) / (lam * n2);
        double c0d = beta * w0, c1d = beta * w1;
        float c0 = (float)c0d, c1 = (float)c1d;
        cbc[0] = c0; cbc[1] = c1;
        o_coeffs[b * 2 + 0] = c0;
        o_coeffs[b * 2 + 1] = c1;
        // analytic r2 = E - 2 c.d + c^T G c  (G = [[A,Bb],[Bb,C]])
        double r2 = E - 2.0 * (c0d * D0 + c1d * D1)
                  + (c0d * c0d * A + 2.0 * c0d * c1d * Bb + c1d * c1d * C);
        o_r2[b] = (float)r2;
    }
    __syncthreads();
    const float c0 = cbc[0];
    const float c1 = cbc[1];

    // ================= Output passes =================
    // smem still holds half 1 -> emit h=1 first (no restage), then h=0.
    float4* __restrict__ xh4 = (float4*)(o_xhat + (size_t)b * NN);
    float4* __restrict__ rs4 = (float4*)(o_res  + (size_t)b * NN);
    #pragma unroll 1
    for (int p = 0; p < 2; p++) {
        const int h = 1 - p;                 // p=0 -> h=1 (resident), p=1 -> h=0
        if (p == 1) {
            __syncthreads();                 // prior reads done before restage
            stage_half(xs, xr, tid);         // h = 0
            __syncthreads();
        }
        const float b2 = base2[h];
        float ps = 0.f;
        float4 cur = xt4[0];
        const int o4 = h * (HALF / 4) + tid * (EPT / 4);
        #pragma unroll
        for (int g = 0; g < 8; g++) {
            float4 nxt;
            if (g < 7) nxt = xt4[g + 1];
            else { nxt.x = xs[blast]; nxt.y = nxt.z = nxt.w = 0.f; }
            float e[4] = {cur.y, cur.z, cur.w, nxt.x};
            float hv[4], rv[4];
            #pragma unroll
            for (int m = 0; m < 4; m++) {
                float xc = e[m];
                ps += xc;
                float u  = fmaf(-0.5f, xc, b2 + ps);
                float su = rhalf ? fsqrt_a(u) : fex2_a(r * flg2_a(u));
                float xv = fmaf(c0, u, c1 * su);
                hv[m] = xv; rv[m] = xc - xv;
            }
            xh4[o4 + g] = make_float4(hv[0], hv[1], hv[2], hv[3]);
            rs4[o4 + g] = make_float4(rv[0], rv[1], rv[2], rv[3]);
            cur = nxt;
        }
    }
}

extern "C" void kernel_launch(void* const* d_in, const int* in_sizes, int n_in,
                              void* d_out, int out_size)
{
    const float* x      = (const float*)d_in[0];
    const float* params = (const float*)d_in[1];
    if (n_in >= 2 && in_sizes[0] == 2) {       // defensive: metadata order swap
        x      = (const float*)d_in[1];
        params = (const float*)d_in[0];
    }
    float* out      = (float*)d_out;
    float* o_coeffs = out;                                   // 512*1*2
    float* o_xhat   = out + (size_t)BATCH * 2;               // 512*1*16384
    float* o_res    = o_xhat + (size_t)BATCH * NN;           // 512*1*16384
    float* o_r2     = o_res  + (size_t)BATCH * NN;           // 512*1

    size_t smem = SMEM_FLOATS * sizeof(float);
    cudaFuncSetAttribute(vp_kernel, cudaFuncAttributeMaxDynamicSharedMemorySize,
                         (int)smem);
    vp_kernel<<<BATCH, THREADS, smem>>>(x, params, o_coeffs, o_xhat, o_res, o_r2);
}